// round 3
// baseline (speedup 1.0000x reference)
#include <cuda_runtime.h>

// ---------------------------------------------------------------------------
// ScaledDotProductAttention: Round 1 baseline (pure fp32, tiled SIMT SGEMM)
//
//   WQ = rnn_ht @ W          [16384,1024] = [16384,1024]x[1024,1024]   (NN)
//   WK = Lt @ kernel[0]      same shape                                 (NN)
//   WV = Lt @ kernel[1]      same shape                                 (NN)
//   QK = WQ @ WK^T per batch [2048,2048], K=1024                        (NT)
//   weights = softmax(QK * 0.125) rowwise            -> d_out[ctx_sz..]
//   context = weights @ WV per batch [2048,1024], K=2048                (NN)
//                                                    -> d_out[0..ctx_sz)
// ---------------------------------------------------------------------------

#define TILE  128
#define KTILE 8

static const long long CTX_ELEMS = 8LL * 2048 * 1024;   // 16,777,216
static const long long WTS_ELEMS = 8LL * 2048 * 2048;   // 33,554,432

// Scratch (allocation-free rule: __device__ globals)
__device__ float g_WQ[8 * 2048 * 1024];
__device__ float g_WK[8 * 2048 * 1024];
__device__ float g_WV[8 * 2048 * 1024];

// Tiled SGEMM: C[M,N] = A[M,K] * B (NN: B is [K,N] row-major, NT: B is [N,K] row-major)
// Batched via blockIdx.z with element strides sA/sB/sC.
template <bool TB>
__global__ __launch_bounds__(256) void sgemm_kernel(
    const float* __restrict__ A,
    const float* __restrict__ B,
    float*       __restrict__ C,
    int M, int N, int K,
    long long sA, long long sB, long long sC)
{
    __shared__ float As[KTILE][TILE];
    __shared__ float Bs[KTILE][TILE];

    const int tid = threadIdx.x;
    const int tx  = tid & 15;   // 0..15  -> 8 columns each
    const int ty  = tid >> 4;   // 0..15  -> 8 rows each

    const long long bz = blockIdx.z;
    A += bz * sA;
    B += bz * sB;
    C += bz * sC;

    const int row0 = blockIdx.y * TILE;
    const int col0 = blockIdx.x * TILE;

    // A-tile loader: 128 rows x 8 k, one float4 per thread (transposed store)
    const int la_r = tid >> 1;        // 0..127
    const int la_c = (tid & 1) * 4;   // 0 or 4
    // B-tile loader (NN): 8 k-rows x 128 n, one float4 per thread
    const int lb_r = tid >> 5;        // 0..7
    const int lb_c = (tid & 31) * 4;  // 0..124

    float acc[8][8];
#pragma unroll
    for (int i = 0; i < 8; ++i)
#pragma unroll
        for (int j = 0; j < 8; ++j) acc[i][j] = 0.0f;

    for (int k0 = 0; k0 < K; k0 += KTILE) {
        // ---- load A tile (always [M,K] row-major), store transposed ----
        {
            const float4 av = *(const float4*)&A[(long long)(row0 + la_r) * K + k0 + la_c];
            As[la_c + 0][la_r] = av.x;
            As[la_c + 1][la_r] = av.y;
            As[la_c + 2][la_r] = av.z;
            As[la_c + 3][la_r] = av.w;
        }
        // ---- load B tile ----
        if (!TB) {
            const float4 bv = *(const float4*)&B[(long long)(k0 + lb_r) * N + col0 + lb_c];
            *(float4*)&Bs[lb_r][lb_c] = bv;
        } else {
            const float4 bv = *(const float4*)&B[(long long)(col0 + la_r) * K + k0 + la_c];
            Bs[la_c + 0][la_r] = bv.x;
            Bs[la_c + 1][la_r] = bv.y;
            Bs[la_c + 2][la_r] = bv.z;
            Bs[la_c + 3][la_r] = bv.w;
        }
        __syncthreads();

#pragma unroll
        for (int k = 0; k < KTILE; ++k) {
            const float4 a0 = *(const float4*)&As[k][ty * 8];
            const float4 a1 = *(const float4*)&As[k][ty * 8 + 4];
            const float4 b0 = *(const float4*)&Bs[k][tx * 8];
            const float4 b1 = *(const float4*)&Bs[k][tx * 8 + 4];
            const float a[8] = {a0.x, a0.y, a0.z, a0.w, a1.x, a1.y, a1.z, a1.w};
            const float b[8] = {b0.x, b0.y, b0.z, b0.w, b1.x, b1.y, b1.z, b1.w};
#pragma unroll
            for (int i = 0; i < 8; ++i)
#pragma unroll
                for (int j = 0; j < 8; ++j)
                    acc[i][j] = fmaf(a[i], b[j], acc[i][j]);
        }
        __syncthreads();
    }

    // ---- write C (vectorized, all dims are multiples of the tile) ----
#pragma unroll
    for (int i = 0; i < 8; ++i) {
        float* crow = &C[(long long)(row0 + ty * 8 + i) * N + col0 + tx * 8];
        *(float4*)&crow[0] = make_float4(acc[i][0], acc[i][1], acc[i][2], acc[i][3]);
        *(float4*)&crow[4] = make_float4(acc[i][4], acc[i][5], acc[i][6], acc[i][7]);
    }
}

// Row softmax in place over ncols=2048 with pre-scale. One block per row.
__global__ __launch_bounds__(256) void softmax_rows_kernel(
    float* __restrict__ data, float scale)
{
    __shared__ float sred[256];
    const int tid = threadIdx.x;
    float* row = data + (long long)blockIdx.x * 2048;

    float v[8];
    float m = -1e30f;
#pragma unroll
    for (int i = 0; i < 8; ++i) {
        v[i] = row[i * 256 + tid] * scale;
        m = fmaxf(m, v[i]);
    }
    sred[tid] = m;
    __syncthreads();
    for (int s = 128; s > 0; s >>= 1) {
        if (tid < s) sred[tid] = fmaxf(sred[tid], sred[tid + s]);
        __syncthreads();
    }
    m = sred[0];
    __syncthreads();

    float sum = 0.0f;
#pragma unroll
    for (int i = 0; i < 8; ++i) {
        v[i] = expf(v[i] - m);
        sum += v[i];
    }
    sred[tid] = sum;
    __syncthreads();
    for (int s = 128; s > 0; s >>= 1) {
        if (tid < s) sred[tid] += sred[tid + s];
        __syncthreads();
    }
    const float inv = 1.0f / sred[0];
#pragma unroll
    for (int i = 0; i < 8; ++i)
        row[i * 256 + tid] = v[i] * inv;
}

extern "C" void kernel_launch(void* const* d_in, const int* in_sizes, int n_in,
                              void* d_out, int out_size)
{
    // metadata order: Lt, rnn_ht, kernel, W
    const float* Lt   = (const float*)d_in[0];   // [8, 2048, 1024]
    const float* rnn  = (const float*)d_in[1];   // [8, 2048, 1024]
    const float* kern = (const float*)d_in[2];   // [2, 1024, 1024]
    const float* W    = (const float*)d_in[3];   // [1024, 1024]

    float* ctx = (float*)d_out;                  // [8, 2048, 1024]
    float* wts = (float*)d_out + CTX_ELEMS;      // [8, 2048, 2048]

    float *wq, *wk, *wv;
    cudaGetSymbolAddress((void**)&wq, g_WQ);
    cudaGetSymbolAddress((void**)&wk, g_WK);
    cudaGetSymbolAddress((void**)&wv, g_WV);

    const dim3 blk(256);

    // Stage 1: projections, batched dims flattened to [16384, 1024]
    sgemm_kernel<false><<<dim3(8, 128, 1), blk>>>(rnn, W,                 wq, 16384, 1024, 1024, 0, 0, 0);
    sgemm_kernel<false><<<dim3(8, 128, 1), blk>>>(Lt,  kern,              wk, 16384, 1024, 1024, 0, 0, 0);
    sgemm_kernel<false><<<dim3(8, 128, 1), blk>>>(Lt,  kern + 1024 * 1024, wv, 16384, 1024, 1024, 0, 0, 0);

    // Stage 2: QK = WQ @ WK^T per batch -> weights slab of d_out
    sgemm_kernel<true><<<dim3(16, 16, 8), blk>>>(wq, wk, wts, 2048, 2048, 1024,
                                                 2048LL * 1024, 2048LL * 1024, 2048LL * 2048);

    // Stage 3: softmax(QK * 1/sqrt(64)) in place
    softmax_rows_kernel<<<16384, blk>>>(wts, 0.125f);

    // Stage 4: context = weights @ WV per batch -> context slab of d_out
    sgemm_kernel<false><<<dim3(8, 16, 8), blk>>>(wts, wv, ctx, 2048, 1024, 2048,
                                                 2048LL * 2048, 2048LL * 1024, 2048LL * 1024);
}

// round 5
// speedup vs baseline: 2.5442x; 2.5442x over previous
#include <cuda_runtime.h>
#include <cuda_fp16.h>
#include <stdint.h>

// ===========================================================================
// ScaledDotProductAttention R5: mma.sync (HMMA) fp16x3 split-precision GEMMs
// (tcgen05/TMA are 'a'-suffix gated and this harness compiles for bare sm_103)
//
//   WQ = rnn @ W, WK = Lt @ k0, WV = Lt @ k1   [16384,1024] K=1024
//   QK = WQ @ WK^T (per batch, NT)             [2048,2048]  K=1024
//   weights = softmax(QK * 0.125)
//   ctx = weights @ WV (per batch, NN)         [2048,1024]  K=2048
//
// Every GEMM: D_fp32 = Ah*Bh + Ah*Bl + Al*Bh  (fp16 hi/lo split, fp32 accum)
// ===========================================================================

#define NB 8
static const long long CTX_ELEMS = 8LL * 2048 * 1024;  // 16,777,216

// ---------------- device scratch (allocation-free rule) --------------------
#define NME (8 * 2048 * 1024)
__device__ __align__(128) __half g_rnn_h[NME], g_rnn_l[NME];
__device__ __align__(128) __half g_Lt_h[NME],  g_Lt_l[NME];
__device__ __align__(128) __half g_Wt_h[1024*1024],  g_Wt_l[1024*1024];
__device__ __align__(128) __half g_k0t_h[1024*1024], g_k0t_l[1024*1024];
__device__ __align__(128) __half g_k1t_h[1024*1024], g_k1t_l[1024*1024];
__device__ __align__(128) __half g_WQ_h[NME], g_WQ_l[NME];
__device__ __align__(128) __half g_WK_h[NME], g_WK_l[NME];
__device__ __align__(128) float  g_WVf[NME];
__device__ __align__(128) __half g_WVt_h[NME], g_WVt_l[NME];
__device__ __align__(128) __half g_w_h[8LL*2048*2048], g_w_l[8LL*2048*2048];

// ---------------- helpers --------------------------------------------------
__device__ __forceinline__ uint32_t smem_u32(const void* p) {
    uint32_t a;
    asm("{ .reg .u64 t; cvta.to.shared.u64 t, %1; cvt.u32.u64 %0, t; }"
        : "=r"(a) : "l"(p));
    return a;
}
__device__ __forceinline__ void ldm4(uint32_t (&r)[4], uint32_t a) {
    asm volatile("ldmatrix.sync.aligned.m8n8.x4.shared.b16 {%0,%1,%2,%3}, [%4];"
        : "=r"(r[0]), "=r"(r[1]), "=r"(r[2]), "=r"(r[3]) : "r"(a));
}
__device__ __forceinline__ void mma16816(float* c, const uint32_t* a,
                                         uint32_t b0, uint32_t b1) {
    asm volatile("mma.sync.aligned.m16n8k16.row.col.f32.f16.f16.f32 "
        "{%0,%1,%2,%3}, {%4,%5,%6,%7}, {%8,%9}, {%0,%1,%2,%3};"
        : "+f"(c[0]), "+f"(c[1]), "+f"(c[2]), "+f"(c[3])
        : "r"(a[0]), "r"(a[1]), "r"(a[2]), "r"(a[3]), "r"(b0), "r"(b1));
}
__device__ __forceinline__ void cpasync16(uint32_t s, const void* g) {
    asm volatile("cp.async.cg.shared.global [%0], [%1], 16;" :: "r"(s), "l"(g));
}

// ---------------- fp16x3 HMMA GEMM -----------------------------------------
// C[M,N] = A[M,K] @ B[N,K]^T, A/B as fp16 hi/lo pairs, both K-major.
// CTA tile 128x128, 8 warps (warp tile 32x64), K-tile 32, 2-stage cp.async.
// Smem per operand-half per stage: 128 rows * 80B (32 halves + 16B pad) = 10240B.
#define OP_BYTES    10240
#define STAGE_BYTES (4 * OP_BYTES)       // Ah, Al, Bh, Bl
#define GEMM_SMEM   (2 * STAGE_BYTES)    // 81920

template <int EPI>  // 0: fp32 C   1: fp16 hi/lo (Ch, Cl)
__global__ __launch_bounds__(256) void gemm_hmma_x3(
    const __half* __restrict__ Ah, const __half* __restrict__ Al,
    const __half* __restrict__ Bh, const __half* __restrict__ Bl,
    float* __restrict__ C, __half* __restrict__ Ch, __half* __restrict__ Cl,
    int K, int ldc, long long sA, long long sB, long long sC)
{
    extern __shared__ char smem[];
    const uint32_t sbase = smem_u32(smem);
    const int tid  = threadIdx.x;
    const int lane = tid & 31, wid = tid >> 5;
    const int wm = wid & 3, wn = wid >> 2;   // warp grid 4(m) x 2(n)
    const long long bz = blockIdx.z;
    Ah += bz * sA; Al += bz * sA;
    Bh += bz * sB; Bl += bz * sB;
    const int row0 = blockIdx.y * 128;
    const int col0 = blockIdx.x * 128;

    float acc[2][8][4];
#pragma unroll
    for (int i = 0; i < 2; ++i)
#pragma unroll
        for (int j = 0; j < 8; ++j)
#pragma unroll
            for (int q = 0; q < 4; ++q) acc[i][j][q] = 0.0f;

    // stage loader: 4 operands x 512 x 16B chunks, 8 cp.async per thread
    auto load_stage = [&](int st, int k0) {
        const uint32_t base = sbase + st * STAGE_BYTES;
#pragma unroll
        for (int j = 0; j < 8; ++j) {
            const int op  = j >> 1;                 // 0:Ah 1:Al 2:Bh 3:Bl
            const int idx = ((j & 1) << 8) + tid;   // 0..511
            const int r = idx >> 2, c = idx & 3;    // row 0..127, 16B chunk 0..3
            const __half* gp = (op == 0) ? Ah : (op == 1) ? Al
                             : (op == 2) ? Bh : Bl;
            const int gr = ((op < 2) ? row0 : col0) + r;
            cpasync16(base + op * OP_BYTES + r * 80 + c * 16,
                      gp + (long long)gr * K + k0 + c * 8);
        }
        asm volatile("cp.async.commit_group;");
    };

    const int ntiles = K >> 5;
    load_stage(0, 0);

    for (int kt = 0; kt < ntiles; ++kt) {
        if (kt + 1 < ntiles) {
            load_stage((kt + 1) & 1, (kt + 1) << 5);
            asm volatile("cp.async.wait_group 1;" ::: "memory");
        } else {
            asm volatile("cp.async.wait_group 0;" ::: "memory");
        }
        __syncthreads();

        const uint32_t st = sbase + (kt & 1) * STAGE_BYTES;
        const uint32_t sAh = st, sAl = st + OP_BYTES;
        const uint32_t sBh = st + 2 * OP_BYTES, sBl = st + 3 * OP_BYTES;
        // lane part of the ldmatrix address: row = lane%16, k-sub = lane/16
        const uint32_t lrow = (lane & 15) * 80 + (lane >> 4) * 16;

#pragma unroll
        for (int ks = 0; ks < 2; ++ks) {
            uint32_t afh[2][4], afl[2][4];
#pragma unroll
            for (int mt = 0; mt < 2; ++mt) {
                const uint32_t ao = (uint32_t)(wm * 32 + mt * 16) * 80 + ks * 32 + lrow;
                ldm4(afh[mt], sAh + ao);
                ldm4(afl[mt], sAl + ao);
            }
#pragma unroll
            for (int p = 0; p < 4; ++p) {
                uint32_t bfh[4], bfl[4];
                const uint32_t bo = (uint32_t)(wn * 64 + p * 16) * 80 + ks * 32 + lrow;
                ldm4(bfh, sBh + bo);
                ldm4(bfl, sBl + bo);
                // bf[0],bf[2] = n-tile 2p (k0,k8); bf[1],bf[3] = n-tile 2p+1
#pragma unroll
                for (int mt = 0; mt < 2; ++mt) {
                    mma16816(acc[mt][2*p],   afh[mt], bfh[0], bfh[2]);  // hi*hi
                    mma16816(acc[mt][2*p+1], afh[mt], bfh[1], bfh[3]);
                    mma16816(acc[mt][2*p],   afh[mt], bfl[0], bfl[2]);  // hi*lo
                    mma16816(acc[mt][2*p+1], afh[mt], bfl[1], bfl[3]);
                    mma16816(acc[mt][2*p],   afl[mt], bfh[0], bfh[2]);  // lo*hi
                    mma16816(acc[mt][2*p+1], afl[mt], bfh[1], bfh[3]);
                }
            }
        }
        __syncthreads();
    }

    // epilogue: fragment m16n8 lane map: rows l/4 and l/4+8, cols 2*(l%4)
    const int l4 = lane >> 2, l2 = (lane & 3) * 2;
#pragma unroll
    for (int mt = 0; mt < 2; ++mt) {
#pragma unroll
        for (int nt = 0; nt < 8; ++nt) {
            const int r  = row0 + wm * 32 + mt * 16 + l4;
            const int cc = col0 + wn * 64 + nt * 8 + l2;
            const long long o0 = bz * sC + (long long)r * ldc + cc;
            const long long o1 = o0 + 8LL * ldc;
            const float* a = acc[mt][nt];
            if (EPI == 0) {
                *(float2*)(C + o0) = make_float2(a[0], a[1]);
                *(float2*)(C + o1) = make_float2(a[2], a[3]);
            } else {
                __half2 hh, ll;
                hh.x = __float2half(a[0]); hh.y = __float2half(a[1]);
                ll.x = __float2half(a[0] - __half2float(hh.x));
                ll.y = __float2half(a[1] - __half2float(hh.y));
                *(__half2*)(Ch + o0) = hh;
                *(__half2*)(Cl + o0) = ll;
                hh.x = __float2half(a[2]); hh.y = __float2half(a[3]);
                ll.x = __float2half(a[2] - __half2float(hh.x));
                ll.y = __float2half(a[3] - __half2float(hh.y));
                *(__half2*)(Ch + o1) = hh;
                *(__half2*)(Cl + o1) = ll;
            }
        }
    }
}

// ---------------- fp32 -> hi/lo fp16 split (elementwise) -------------------
__global__ __launch_bounds__(256) void split_kernel(
    const float* __restrict__ x, __half* __restrict__ h, __half* __restrict__ l)
{
    const long long i0 = ((long long)blockIdx.x * 256 + threadIdx.x) * 8;
#pragma unroll
    for (int v = 0; v < 2; ++v) {
        const float4 f = *(const float4*)(x + i0 + v * 4);
        const float ff[4] = {f.x, f.y, f.z, f.w};
        __half hh[4], ll[4];
#pragma unroll
        for (int j = 0; j < 4; ++j) {
            hh[j] = __float2half(ff[j]);
            ll[j] = __float2half(ff[j] - __half2float(hh[j]));
        }
        *(uint2*)(h + i0 + v * 4) = *(uint2*)hh;
        *(uint2*)(l + i0 + v * 4) = *(uint2*)ll;
    }
}

// ---------------- fp32 [R,C] -> transposed hi/lo fp16 [C,R] ----------------
__global__ __launch_bounds__(256) void splitT_kernel(
    const float* __restrict__ in, __half* __restrict__ oh,
    __half* __restrict__ ol, int R, int C, long long sIn, long long sOut)
{
    __shared__ float t[32][33];
    const long long bz = blockIdx.z;
    in += bz * sIn; oh += bz * sOut; ol += bz * sOut;
    const int c0 = blockIdx.x * 32, r0 = blockIdx.y * 32;
    const int tx = threadIdx.x & 31, ty = threadIdx.x >> 5;  // 32 x 8
#pragma unroll
    for (int i = 0; i < 4; ++i)
        t[ty + 8 * i][tx] = in[(long long)(r0 + ty + 8 * i) * C + c0 + tx];
    __syncthreads();
#pragma unroll
    for (int i = 0; i < 4; ++i) {
        const float v = t[tx][ty + 8 * i];
        const __half h = __float2half(v);
        const long long o = (long long)(c0 + ty + 8 * i) * R + r0 + tx;
        oh[o] = h;
        ol[o] = __float2half(v - __half2float(h));
    }
}

// ---------------- softmax rows (2048) + hi/lo fp16 split -------------------
__global__ __launch_bounds__(256) void softmax_split_kernel(
    float* __restrict__ data, __half* __restrict__ wh,
    __half* __restrict__ wl, float scale)
{
    __shared__ float sred[256];
    const int tid = threadIdx.x;
    const long long rb = (long long)blockIdx.x * 2048;
    float* row = data + rb;

    float v[8];
    float m = -1e30f;
#pragma unroll
    for (int i = 0; i < 8; ++i) {
        v[i] = row[i * 256 + tid] * scale;
        m = fmaxf(m, v[i]);
    }
    sred[tid] = m;
    __syncthreads();
    for (int s = 128; s > 0; s >>= 1) {
        if (tid < s) sred[tid] = fmaxf(sred[tid], sred[tid + s]);
        __syncthreads();
    }
    m = sred[0];
    __syncthreads();

    float sum = 0.0f;
#pragma unroll
    for (int i = 0; i < 8; ++i) {
        v[i] = expf(v[i] - m);
        sum += v[i];
    }
    sred[tid] = sum;
    __syncthreads();
    for (int s = 128; s > 0; s >>= 1) {
        if (tid < s) sred[tid] += sred[tid + s];
        __syncthreads();
    }
    const float inv = 1.0f / sred[0];
#pragma unroll
    for (int i = 0; i < 8; ++i) {
        const float w = v[i] * inv;
        row[i * 256 + tid] = w;
        const __half h = __float2half(w);
        wh[rb + i * 256 + tid] = h;
        wl[rb + i * 256 + tid] = __float2half(w - __half2float(h));
    }
}

// ---------------------------------------------------------------------------
extern "C" void kernel_launch(void* const* d_in, const int* in_sizes, int n_in,
                              void* d_out, int out_size)
{
    const float* Lt   = (const float*)d_in[0];   // [8, 2048, 1024]
    const float* rnn  = (const float*)d_in[1];   // [8, 2048, 1024]
    const float* kern = (const float*)d_in[2];   // [2, 1024, 1024]
    const float* W    = (const float*)d_in[3];   // [1024, 1024]

    float* ctx = (float*)d_out;                  // [8, 2048, 1024]
    float* wts = (float*)d_out + CTX_ELEMS;      // [8, 2048, 2048]

    __half *rnnh, *rnnl, *lth, *ltl, *wth, *wtl, *k0h, *k0l, *k1h, *k1l;
    __half *wqh, *wql, *wkh, *wkl, *wvth, *wvtl, *wh, *wl;
    float* wvf;
    cudaGetSymbolAddress((void**)&rnnh, g_rnn_h); cudaGetSymbolAddress((void**)&rnnl, g_rnn_l);
    cudaGetSymbolAddress((void**)&lth,  g_Lt_h);  cudaGetSymbolAddress((void**)&ltl,  g_Lt_l);
    cudaGetSymbolAddress((void**)&wth,  g_Wt_h);  cudaGetSymbolAddress((void**)&wtl,  g_Wt_l);
    cudaGetSymbolAddress((void**)&k0h,  g_k0t_h); cudaGetSymbolAddress((void**)&k0l,  g_k0t_l);
    cudaGetSymbolAddress((void**)&k1h,  g_k1t_h); cudaGetSymbolAddress((void**)&k1l,  g_k1t_l);
    cudaGetSymbolAddress((void**)&wqh,  g_WQ_h);  cudaGetSymbolAddress((void**)&wql,  g_WQ_l);
    cudaGetSymbolAddress((void**)&wkh,  g_WK_h);  cudaGetSymbolAddress((void**)&wkl,  g_WK_l);
    cudaGetSymbolAddress((void**)&wvf,  g_WVf);
    cudaGetSymbolAddress((void**)&wvth, g_WVt_h); cudaGetSymbolAddress((void**)&wvtl, g_WVt_l);
    cudaGetSymbolAddress((void**)&wh,   g_w_h);   cudaGetSymbolAddress((void**)&wl,   g_w_l);

    cudaFuncSetAttribute(gemm_hmma_x3<0>, cudaFuncAttributeMaxDynamicSharedMemorySize, GEMM_SMEM);
    cudaFuncSetAttribute(gemm_hmma_x3<1>, cudaFuncAttributeMaxDynamicSharedMemorySize, GEMM_SMEM);

    // 1) split activations into fp16 hi/lo
    split_kernel<<<8192, 256>>>(rnn, rnnh, rnnl);
    split_kernel<<<8192, 256>>>(Lt, lth, ltl);
    // 2) transpose + split weight matrices -> [N, K] K-major
    splitT_kernel<<<dim3(32, 32, 1), 256>>>(W, wth, wtl, 1024, 1024, 0, 0);
    splitT_kernel<<<dim3(32, 32, 1), 256>>>(kern, k0h, k0l, 1024, 1024, 0, 0);
    splitT_kernel<<<dim3(32, 32, 1), 256>>>(kern + 1024 * 1024, k1h, k1l, 1024, 1024, 0, 0);

    // 3) projections: M=16384, N=1024, K=1024
    gemm_hmma_x3<1><<<dim3(8, 128, 1), 256, GEMM_SMEM>>>(
        rnnh, rnnl, wth, wtl, nullptr, wqh, wql, 1024, 1024, 0, 0, 0);
    gemm_hmma_x3<1><<<dim3(8, 128, 1), 256, GEMM_SMEM>>>(
        lth, ltl, k0h, k0l, nullptr, wkh, wkl, 1024, 1024, 0, 0, 0);
    gemm_hmma_x3<0><<<dim3(8, 128, 1), 256, GEMM_SMEM>>>(
        lth, ltl, k1h, k1l, wvf, nullptr, nullptr, 1024, 1024, 0, 0, 0);

    // 4) transpose + split WV: per batch [2048,1024] -> [1024,2048] K-major
    splitT_kernel<<<dim3(32, 64, 8), 256>>>(wvf, wvth, wvtl, 2048, 1024,
                                            2048LL * 1024, 2048LL * 1024);

    // 5) QK = WQ @ WK^T per batch -> fp32 wts slab of d_out
    gemm_hmma_x3<0><<<dim3(16, 16, 8), 256, GEMM_SMEM>>>(
        wqh, wql, wkh, wkl, wts, nullptr, nullptr, 1024, 2048,
        2048LL * 1024, 2048LL * 1024, 2048LL * 2048);

    // 6) softmax(QK * 0.125) in place + fp16 hi/lo split for context GEMM
    softmax_split_kernel<<<16384, 256>>>(wts, wh, wl, 0.125f);

    // 7) ctx = weights @ WV per batch (B = WVt hi/lo, K-major), K=2048
    gemm_hmma_x3<0><<<dim3(8, 16, 8), 256, GEMM_SMEM>>>(
        wh, wl, wvth, wvtl, ctx, nullptr, nullptr, 2048, 1024,
        2048LL * 2048, 1024LL * 2048, 2048LL * 1024);
}

// round 6
// speedup vs baseline: 2.8890x; 1.1355x over previous
#include <cuda_runtime.h>
#include <cuda_fp16.h>
#include <stdint.h>

// ===========================================================================
// ScaledDotProductAttention R6: HMMA fp16x3 + associativity + fused WV^T
//
//   P  = k0 @ W^T                    [1024,1024]   (tiny)
//   T  = rnn @ P^T                   [16384,1024]  (== WQ @ (W k0^T) chain)
//   WVt= (Lt @ k1)^T per batch       [1024,2048]   (EPI2 fused transpose)
//   QK = T @ Lt^T per batch          [2048,2048]
//   weights = softmax(QK * 0.125)    -> d_out
//   ctx = weights @ WVt^T per batch  [2048,1024]   -> d_out
//
// Every GEMM: D_fp32 = Ah*Bh + Ah*Bl + Al*Bh  (fp16 hi/lo split, fp32 accum)
// ===========================================================================

#define NB 8
static const long long CTX_ELEMS = 8LL * 2048 * 1024;  // 16,777,216

// ---------------- device scratch (allocation-free rule) --------------------
#define NME (8 * 2048 * 1024)
__device__ __align__(128) __half g_rnn_h[NME], g_rnn_l[NME];
__device__ __align__(128) __half g_Lt_h[NME],  g_Lt_l[NME];
__device__ __align__(128) __half g_W_h[1024*1024],   g_W_l[1024*1024];
__device__ __align__(128) __half g_k0_h[1024*1024],  g_k0_l[1024*1024];
__device__ __align__(128) __half g_k1t_h[1024*1024], g_k1t_l[1024*1024];
__device__ __align__(128) __half g_P_h[1024*1024],   g_P_l[1024*1024];
__device__ __align__(128) __half g_T_h[NME], g_T_l[NME];
__device__ __align__(128) __half g_WVt_h[NME], g_WVt_l[NME];
__device__ __align__(128) __half g_w_h[8LL*2048*2048], g_w_l[8LL*2048*2048];

// ---------------- helpers --------------------------------------------------
__device__ __forceinline__ uint32_t smem_u32(const void* p) {
    uint32_t a;
    asm("{ .reg .u64 t; cvta.to.shared.u64 t, %1; cvt.u32.u64 %0, t; }"
        : "=r"(a) : "l"(p));
    return a;
}
__device__ __forceinline__ void ldm4(uint32_t (&r)[4], uint32_t a) {
    asm volatile("ldmatrix.sync.aligned.m8n8.x4.shared.b16 {%0,%1,%2,%3}, [%4];"
        : "=r"(r[0]), "=r"(r[1]), "=r"(r[2]), "=r"(r[3]) : "r"(a));
}
__device__ __forceinline__ void mma16816(float* c, const uint32_t* a,
                                         uint32_t b0, uint32_t b1) {
    asm volatile("mma.sync.aligned.m16n8k16.row.col.f32.f16.f16.f32 "
        "{%0,%1,%2,%3}, {%4,%5,%6,%7}, {%8,%9}, {%0,%1,%2,%3};"
        : "+f"(c[0]), "+f"(c[1]), "+f"(c[2]), "+f"(c[3])
        : "r"(a[0]), "r"(a[1]), "r"(a[2]), "r"(a[3]), "r"(b0), "r"(b1));
}
__device__ __forceinline__ void cpasync16(uint32_t s, const void* g) {
    asm volatile("cp.async.cg.shared.global [%0], [%1], 16;" :: "r"(s), "l"(g));
}

// ---------------- fp16x3 HMMA GEMM -----------------------------------------
// C[M,N] = A[M,K] @ B[N,K]^T, A/B as fp16 hi/lo pairs, both K-major.
// CTA tile 128x128, 8 warps (warp tile 32x64), K-tile 32, 2-stage cp.async.
#define OP_BYTES    10240
#define STAGE_BYTES (4 * OP_BYTES)       // Ah, Al, Bh, Bl
#define GEMM_SMEM   (2 * STAGE_BYTES)    // 81920

// EPI 0: fp32 C.  EPI 1: fp16 hi/lo (Ch, Cl).
// EPI 2: transposed fp16 hi/lo per batch of 2048 rows: out[e, s] (ld 2048).
template <int EPI>
__global__ __launch_bounds__(256) void gemm_hmma_x3(
    const __half* __restrict__ Ah, const __half* __restrict__ Al,
    const __half* __restrict__ Bh, const __half* __restrict__ Bl,
    float* __restrict__ C, __half* __restrict__ Ch, __half* __restrict__ Cl,
    int K, int ldc, long long sA, long long sB, long long sC)
{
    extern __shared__ char smem[];
    const uint32_t sbase = smem_u32(smem);
    const int tid  = threadIdx.x;
    const int lane = tid & 31, wid = tid >> 5;
    const int wm = wid & 3, wn = wid >> 2;   // warp grid 4(m) x 2(n)
    const long long bz = blockIdx.z;
    Ah += bz * sA; Al += bz * sA;
    Bh += bz * sB; Bl += bz * sB;
    const int row0 = blockIdx.y * 128;
    const int col0 = blockIdx.x * 128;

    float acc[2][8][4];
#pragma unroll
    for (int i = 0; i < 2; ++i)
#pragma unroll
        for (int j = 0; j < 8; ++j)
#pragma unroll
            for (int q = 0; q < 4; ++q) acc[i][j][q] = 0.0f;

    auto load_stage = [&](int st, int k0) {
        const uint32_t base = sbase + st * STAGE_BYTES;
#pragma unroll
        for (int j = 0; j < 8; ++j) {
            const int op  = j >> 1;                 // 0:Ah 1:Al 2:Bh 3:Bl
            const int idx = ((j & 1) << 8) + tid;   // 0..511
            const int r = idx >> 2, c = idx & 3;    // row 0..127, 16B chunk
            const __half* gp = (op == 0) ? Ah : (op == 1) ? Al
                             : (op == 2) ? Bh : Bl;
            const int gr = ((op < 2) ? row0 : col0) + r;
            cpasync16(base + op * OP_BYTES + r * 80 + c * 16,
                      gp + (long long)gr * K + k0 + c * 8);
        }
        asm volatile("cp.async.commit_group;");
    };

    const int ntiles = K >> 5;
    load_stage(0, 0);

    for (int kt = 0; kt < ntiles; ++kt) {
        if (kt + 1 < ntiles) {
            load_stage((kt + 1) & 1, (kt + 1) << 5);
            asm volatile("cp.async.wait_group 1;" ::: "memory");
        } else {
            asm volatile("cp.async.wait_group 0;" ::: "memory");
        }
        __syncthreads();

        const uint32_t st = sbase + (kt & 1) * STAGE_BYTES;
        const uint32_t sAh = st, sAl = st + OP_BYTES;
        const uint32_t sBh = st + 2 * OP_BYTES, sBl = st + 3 * OP_BYTES;
        const uint32_t lrow = (lane & 15) * 80 + (lane >> 4) * 16;

#pragma unroll
        for (int ks = 0; ks < 2; ++ks) {
            uint32_t afh[2][4], afl[2][4];
#pragma unroll
            for (int mt = 0; mt < 2; ++mt) {
                const uint32_t ao = (uint32_t)(wm * 32 + mt * 16) * 80 + ks * 32 + lrow;
                ldm4(afh[mt], sAh + ao);
                ldm4(afl[mt], sAl + ao);
            }
#pragma unroll
            for (int p = 0; p < 4; ++p) {
                uint32_t bfh[4], bfl[4];
                const uint32_t bo = (uint32_t)(wn * 64 + p * 16) * 80 + ks * 32 + lrow;
                ldm4(bfh, sBh + bo);
                ldm4(bfl, sBl + bo);
#pragma unroll
                for (int mt = 0; mt < 2; ++mt) {
                    mma16816(acc[mt][2*p],   afh[mt], bfh[0], bfh[2]);  // hi*hi
                    mma16816(acc[mt][2*p+1], afh[mt], bfh[1], bfh[3]);
                    mma16816(acc[mt][2*p],   afh[mt], bfl[0], bfl[2]);  // hi*lo
                    mma16816(acc[mt][2*p+1], afh[mt], bfl[1], bfl[3]);
                    mma16816(acc[mt][2*p],   afl[mt], bfh[0], bfh[2]);  // lo*hi
                    mma16816(acc[mt][2*p+1], afl[mt], bfh[1], bfh[3]);
                }
            }
        }
        __syncthreads();
    }

    const int l4 = lane >> 2, l2 = (lane & 3) * 2;

    if (EPI == 2) {
        // Transposed epilogue: stage hi (then lo) tile in smem, write out[e,s].
        __half* sst = (__half*)smem;          // stride 130 halves per m-row
        const int b  = row0 >> 11;            // batch (2048 rows per batch)
        const int s0 = row0 & 2047;
        __half* outs[2] = {Ch, Cl};
#pragma unroll
        for (int pass = 0; pass < 2; ++pass) {
#pragma unroll
            for (int mt = 0; mt < 2; ++mt) {
#pragma unroll
                for (int nt = 0; nt < 8; ++nt) {
                    const int rl = wm * 32 + mt * 16 + l4;
                    const int cl = wn * 64 + nt * 8 + l2;
                    const float* a = acc[mt][nt];
                    __half2 v0, v1;
                    __half h0 = __float2half(a[0]), h1 = __float2half(a[1]);
                    __half h2 = __float2half(a[2]), h3 = __float2half(a[3]);
                    if (pass == 0) {
                        v0 = __halves2half2(h0, h1);
                        v1 = __halves2half2(h2, h3);
                    } else {
                        v0 = __halves2half2(__float2half(a[0] - __half2float(h0)),
                                            __float2half(a[1] - __half2float(h1)));
                        v1 = __halves2half2(__float2half(a[2] - __half2float(h2)),
                                            __float2half(a[3] - __half2float(h3)));
                    }
                    *(__half2*)&sst[rl * 130 + cl]       = v0;
                    *(__half2*)&sst[(rl + 8) * 130 + cl] = v1;
                }
            }
            __syncthreads();
            // warp w writes output rows e = j*8 + w; lane covers s = 4*lane..+3
            __half* op = outs[pass];
#pragma unroll
            for (int j = 0; j < 16; ++j) {
                const int e = j * 8 + wid;
                __half v[4];
#pragma unroll
                for (int q = 0; q < 4; ++q)
                    v[q] = sst[(4 * lane + q) * 130 + e];
                const long long o = (long long)b * (1024LL * 2048) +
                                    (long long)(col0 + e) * 2048 + s0 + 4 * lane;
                *(uint2*)(op + o) = *(uint2*)v;
            }
            __syncthreads();
        }
        return;
    }

#pragma unroll
    for (int mt = 0; mt < 2; ++mt) {
#pragma unroll
        for (int nt = 0; nt < 8; ++nt) {
            const int r  = row0 + wm * 32 + mt * 16 + l4;
            const int cc = col0 + wn * 64 + nt * 8 + l2;
            const long long o0 = bz * sC + (long long)r * ldc + cc;
            const long long o1 = o0 + 8LL * ldc;
            const float* a = acc[mt][nt];
            if (EPI == 0) {
                *(float2*)(C + o0) = make_float2(a[0], a[1]);
                *(float2*)(C + o1) = make_float2(a[2], a[3]);
            } else {
                __half2 hh, ll;
                hh.x = __float2half(a[0]); hh.y = __float2half(a[1]);
                ll.x = __float2half(a[0] - __half2float(hh.x));
                ll.y = __float2half(a[1] - __half2float(hh.y));
                *(__half2*)(Ch + o0) = hh;
                *(__half2*)(Cl + o0) = ll;
                hh.x = __float2half(a[2]); hh.y = __float2half(a[3]);
                ll.x = __float2half(a[2] - __half2float(hh.x));
                ll.y = __float2half(a[3] - __half2float(hh.y));
                *(__half2*)(Ch + o1) = hh;
                *(__half2*)(Cl + o1) = ll;
            }
        }
    }
}

// ---------------- fp32 -> hi/lo fp16 split (elementwise) -------------------
__global__ __launch_bounds__(256) void split_kernel(
    const float* __restrict__ x, __half* __restrict__ h, __half* __restrict__ l)
{
    const long long i0 = ((long long)blockIdx.x * 256 + threadIdx.x) * 8;
#pragma unroll
    for (int v = 0; v < 2; ++v) {
        const float4 f = *(const float4*)(x + i0 + v * 4);
        const float ff[4] = {f.x, f.y, f.z, f.w};
        __half hh[4], ll[4];
#pragma unroll
        for (int j = 0; j < 4; ++j) {
            hh[j] = __float2half(ff[j]);
            ll[j] = __float2half(ff[j] - __half2float(hh[j]));
        }
        *(uint2*)(h + i0 + v * 4) = *(uint2*)hh;
        *(uint2*)(l + i0 + v * 4) = *(uint2*)ll;
    }
}

// ---------------- fp32 [R,C] -> transposed hi/lo fp16 [C,R] ----------------
__global__ __launch_bounds__(256) void splitT_kernel(
    const float* __restrict__ in, __half* __restrict__ oh,
    __half* __restrict__ ol, int R, int C)
{
    __shared__ float t[32][33];
    const int c0 = blockIdx.x * 32, r0 = blockIdx.y * 32;
    const int tx = threadIdx.x & 31, ty = threadIdx.x >> 5;  // 32 x 8
#pragma unroll
    for (int i = 0; i < 4; ++i)
        t[ty + 8 * i][tx] = in[(long long)(r0 + ty + 8 * i) * C + c0 + tx];
    __syncthreads();
#pragma unroll
    for (int i = 0; i < 4; ++i) {
        const float v = t[tx][ty + 8 * i];
        const __half h = __float2half(v);
        const long long o = (long long)(c0 + ty + 8 * i) * R + r0 + tx;
        oh[o] = h;
        ol[o] = __float2half(v - __half2float(h));
    }
}

// ---------------- softmax rows (2048) + hi/lo fp16 split -------------------
__global__ __launch_bounds__(256) void softmax_split_kernel(
    float* __restrict__ data, __half* __restrict__ wh,
    __half* __restrict__ wl, float scale)
{
    __shared__ float sred[256];
    const int tid = threadIdx.x;
    const long long rb = (long long)blockIdx.x * 2048;
    float* row = data + rb;

    float v[8];
    float m = -1e30f;
#pragma unroll
    for (int i = 0; i < 8; ++i) {
        v[i] = row[i * 256 + tid] * scale;
        m = fmaxf(m, v[i]);
    }
    sred[tid] = m;
    __syncthreads();
    for (int s = 128; s > 0; s >>= 1) {
        if (tid < s) sred[tid] = fmaxf(sred[tid], sred[tid + s]);
        __syncthreads();
    }
    m = sred[0];
    __syncthreads();

    float sum = 0.0f;
#pragma unroll
    for (int i = 0; i < 8; ++i) {
        v[i] = expf(v[i] - m);
        sum += v[i];
    }
    sred[tid] = sum;
    __syncthreads();
    for (int s = 128; s > 0; s >>= 1) {
        if (tid < s) sred[tid] += sred[tid + s];
        __syncthreads();
    }
    const float inv = 1.0f / sred[0];
#pragma unroll
    for (int i = 0; i < 8; ++i) {
        const float w = v[i] * inv;
        row[i * 256 + tid] = w;
        const __half h = __float2half(w);
        wh[rb + i * 256 + tid] = h;
        wl[rb + i * 256 + tid] = __float2half(w - __half2float(h));
    }
}

// ---------------------------------------------------------------------------
extern "C" void kernel_launch(void* const* d_in, const int* in_sizes, int n_in,
                              void* d_out, int out_size)
{
    const float* Lt   = (const float*)d_in[0];   // [8, 2048, 1024]
    const float* rnn  = (const float*)d_in[1];   // [8, 2048, 1024]
    const float* kern = (const float*)d_in[2];   // [2, 1024, 1024]
    const float* W    = (const float*)d_in[3];   // [1024, 1024]

    float* ctx = (float*)d_out;                  // [8, 2048, 1024]
    float* wts = (float*)d_out + CTX_ELEMS;      // [8, 2048, 2048]

    __half *rnnh, *rnnl, *lth, *ltl, *wWh, *wWl, *k0h, *k0l, *k1th, *k1tl;
    __half *Ph, *Pl, *Th, *Tl, *wvth, *wvtl, *wh, *wl;
    cudaGetSymbolAddress((void**)&rnnh, g_rnn_h); cudaGetSymbolAddress((void**)&rnnl, g_rnn_l);
    cudaGetSymbolAddress((void**)&lth,  g_Lt_h);  cudaGetSymbolAddress((void**)&ltl,  g_Lt_l);
    cudaGetSymbolAddress((void**)&wWh,  g_W_h);   cudaGetSymbolAddress((void**)&wWl,  g_W_l);
    cudaGetSymbolAddress((void**)&k0h,  g_k0_h);  cudaGetSymbolAddress((void**)&k0l,  g_k0_l);
    cudaGetSymbolAddress((void**)&k1th, g_k1t_h); cudaGetSymbolAddress((void**)&k1tl, g_k1t_l);
    cudaGetSymbolAddress((void**)&Ph,   g_P_h);   cudaGetSymbolAddress((void**)&Pl,   g_P_l);
    cudaGetSymbolAddress((void**)&Th,   g_T_h);   cudaGetSymbolAddress((void**)&Tl,   g_T_l);
    cudaGetSymbolAddress((void**)&wvth, g_WVt_h); cudaGetSymbolAddress((void**)&wvtl, g_WVt_l);
    cudaGetSymbolAddress((void**)&wh,   g_w_h);   cudaGetSymbolAddress((void**)&wl,   g_w_l);

    cudaFuncSetAttribute(gemm_hmma_x3<0>, cudaFuncAttributeMaxDynamicSharedMemorySize, GEMM_SMEM);
    cudaFuncSetAttribute(gemm_hmma_x3<1>, cudaFuncAttributeMaxDynamicSharedMemorySize, GEMM_SMEM);
    cudaFuncSetAttribute(gemm_hmma_x3<2>, cudaFuncAttributeMaxDynamicSharedMemorySize, GEMM_SMEM);

    // 1) splits: activations + small weight matrices (K-major already)
    split_kernel<<<8192, 256>>>(rnn, rnnh, rnnl);
    split_kernel<<<8192, 256>>>(Lt, lth, ltl);
    split_kernel<<<512, 256>>>(W, wWh, wWl);
    split_kernel<<<512, 256>>>(kern, k0h, k0l);
    splitT_kernel<<<dim3(32, 32, 1), 256>>>(kern + 1024 * 1024, k1th, k1tl, 1024, 1024);

    // 2) P = k0 @ W^T  [1024,1024]  (P[dk,d] = sum_e k0[dk,e] W[d,e])
    gemm_hmma_x3<1><<<dim3(8, 8, 1), 256, GEMM_SMEM>>>(
        k0h, k0l, wWh, wWl, nullptr, Ph, Pl, 1024, 1024, 0, 0, 0);

    // 3) T = rnn @ P^T  [16384,1024]
    gemm_hmma_x3<1><<<dim3(8, 128, 1), 256, GEMM_SMEM>>>(
        rnnh, rnnl, Ph, Pl, nullptr, Th, Tl, 1024, 1024, 0, 0, 0);

    // 4) WVt = (Lt @ k1)^T per batch  (EPI2: fused transpose + split)
    gemm_hmma_x3<2><<<dim3(8, 128, 1), 256, GEMM_SMEM>>>(
        lth, ltl, k1th, k1tl, nullptr, wvth, wvtl, 1024, 0, 0, 0, 0);

    // 5) QK = T @ Lt^T per batch -> fp32 wts slab of d_out
    gemm_hmma_x3<0><<<dim3(16, 16, 8), 256, GEMM_SMEM>>>(
        Th, Tl, lth, ltl, wts, nullptr, nullptr, 1024, 2048,
        2048LL * 1024, 2048LL * 1024, 2048LL * 2048);

    // 6) softmax(QK * 0.125) in place + fp16 hi/lo split for context GEMM
    softmax_split_kernel<<<16384, 256>>>(wts, wh, wl, 0.125f);

    // 7) ctx = weights @ WVt^T per batch, K=2048
    gemm_hmma_x3<0><<<dim3(8, 16, 8), 256, GEMM_SMEM>>>(
        wh, wl, wvth, wvtl, ctx, nullptr, nullptr, 2048, 1024,
        2048LL * 2048, 1024LL * 2048, 2048LL * 1024);
}

// round 7
// speedup vs baseline: 3.5289x; 1.2215x over previous
#include <cuda_runtime.h>
#include <cuda_fp16.h>
#include <stdint.h>

// ===========================================================================
// ScaledDotProductAttention R7: precision-tiered HMMA
//
//   P  = k0 @ W^T                    [1024,1024]  x3
//   T  = rnn @ P^T                   [16384,1024] x3
//   WVt= (Lt @ k1)^T per batch       [1024,2048]  x3, fused transpose+split
//   QK = T @ Lt^T per batch          [2048,2048]  x3  -> fp32
//   weights = softmax(QK * 0.125)    -> d_out (+ fp16 hi for ctx)
//   ctx = weights @ WVt^T per batch  [2048,1024]  x1 (plain fp16) -> d_out
// ===========================================================================

#define NB 8
static const long long CTX_ELEMS = 8LL * 2048 * 1024;  // 16,777,216

// ---------------- device scratch (allocation-free rule) --------------------
#define NME (8 * 2048 * 1024)
__device__ __align__(128) __half g_rnn_h[NME], g_rnn_l[NME];
__device__ __align__(128) __half g_Lt_h[NME],  g_Lt_l[NME];
__device__ __align__(128) __half g_W_h[1024*1024],   g_W_l[1024*1024];
__device__ __align__(128) __half g_k0_h[1024*1024],  g_k0_l[1024*1024];
__device__ __align__(128) __half g_k1t_h[1024*1024], g_k1t_l[1024*1024];
__device__ __align__(128) __half g_P_h[1024*1024],   g_P_l[1024*1024];
__device__ __align__(128) __half g_T_h[NME], g_T_l[NME];
__device__ __align__(128) __half g_WVt_h[NME], g_WVt_l[NME];
__device__ __align__(128) __half g_w_h[8LL*2048*2048];

// ---------------- helpers --------------------------------------------------
__device__ __forceinline__ uint32_t smem_u32(const void* p) {
    uint32_t a;
    asm("{ .reg .u64 t; cvta.to.shared.u64 t, %1; cvt.u32.u64 %0, t; }"
        : "=r"(a) : "l"(p));
    return a;
}
__device__ __forceinline__ void ldm4(uint32_t (&r)[4], uint32_t a) {
    asm volatile("ldmatrix.sync.aligned.m8n8.x4.shared.b16 {%0,%1,%2,%3}, [%4];"
        : "=r"(r[0]), "=r"(r[1]), "=r"(r[2]), "=r"(r[3]) : "r"(a));
}
__device__ __forceinline__ void mma16816(float* c, const uint32_t* a,
                                         uint32_t b0, uint32_t b1) {
    asm volatile("mma.sync.aligned.m16n8k16.row.col.f32.f16.f16.f32 "
        "{%0,%1,%2,%3}, {%4,%5,%6,%7}, {%8,%9}, {%0,%1,%2,%3};"
        : "+f"(c[0]), "+f"(c[1]), "+f"(c[2]), "+f"(c[3])
        : "r"(a[0]), "r"(a[1]), "r"(a[2]), "r"(a[3]), "r"(b0), "r"(b1));
}
__device__ __forceinline__ void cpasync16(uint32_t s, const void* g) {
    asm volatile("cp.async.cg.shared.global [%0], [%1], 16;" :: "r"(s), "l"(g));
}

// ---------------- fp16 HMMA GEMM (NT=3: hi/lo split, NT=1: plain) ----------
// C[M,N] = A[M,K] @ B[N,K]^T, both K-major. CTA tile 128x128, 8 warps
// (warp tile 32x64), K-tile 32, 2-stage cp.async double buffer.
#define OP_BYTES 10240

// EPI 0: fp32 C.  EPI 1: fp16 hi/lo (Ch, Cl).
// EPI 2: transposed fp16 hi/lo per batch of 2048 rows: out[e, s] (ld 2048).
template <int EPI, int NT>
__global__ __launch_bounds__(256) void gemm_hmma(
    const __half* __restrict__ Ah, const __half* __restrict__ Al,
    const __half* __restrict__ Bh, const __half* __restrict__ Bl,
    float* __restrict__ C, __half* __restrict__ Ch, __half* __restrict__ Cl,
    int K, int ldc, long long sA, long long sB, long long sC)
{
    constexpr int NOPS = (NT == 1) ? 2 : 4;
    constexpr uint32_t STAGE = NOPS * OP_BYTES;
    extern __shared__ char smem[];
    const uint32_t sbase = smem_u32(smem);
    const int tid  = threadIdx.x;
    const int lane = tid & 31, wid = tid >> 5;
    const int wm = wid & 3, wn = wid >> 2;   // warp grid 4(m) x 2(n)
    const long long bz = blockIdx.z;
    Ah += bz * sA; Bh += bz * sB;
    if (NT == 3) { Al += bz * sA; Bl += bz * sB; }
    const int row0 = blockIdx.y * 128;
    const int col0 = blockIdx.x * 128;

    float acc[2][8][4];
#pragma unroll
    for (int i = 0; i < 2; ++i)
#pragma unroll
        for (int j = 0; j < 8; ++j)
#pragma unroll
            for (int q = 0; q < 4; ++q) acc[i][j][q] = 0.0f;

    auto load_stage = [&](int st, int k0) {
        const uint32_t base = sbase + st * STAGE;
#pragma unroll
        for (int j = 0; j < 2 * NOPS; ++j) {
            const int op  = j >> 1;                 // NT3: Ah,Al,Bh,Bl  NT1: Ah,Bh
            const int idx = ((j & 1) << 8) + tid;   // 0..511
            const int r = idx >> 2, c = idx & 3;    // row 0..127, 16B chunk
            const __half* gp;
            bool isA;
            if (NT == 1) { isA = (op == 0); gp = isA ? Ah : Bh; }
            else {
                isA = (op < 2);
                gp = (op == 0) ? Ah : (op == 1) ? Al : (op == 2) ? Bh : Bl;
            }
            const int gr = (isA ? row0 : col0) + r;
            cpasync16(base + op * OP_BYTES + r * 80 + c * 16,
                      gp + (long long)gr * K + k0 + c * 8);
        }
        asm volatile("cp.async.commit_group;");
    };

    const int ntiles = K >> 5;
    load_stage(0, 0);

    for (int kt = 0; kt < ntiles; ++kt) {
        if (kt + 1 < ntiles) {
            load_stage((kt + 1) & 1, (kt + 1) << 5);
            asm volatile("cp.async.wait_group 1;" ::: "memory");
        } else {
            asm volatile("cp.async.wait_group 0;" ::: "memory");
        }
        __syncthreads();

        const uint32_t st = sbase + (kt & 1) * STAGE;
        const uint32_t sAh = st;
        const uint32_t sAl = st + OP_BYTES;                       // NT3 only
        const uint32_t sBh = st + (NT == 1 ? 1 : 2) * OP_BYTES;
        const uint32_t sBl = st + 3 * OP_BYTES;                   // NT3 only
        const uint32_t lrow = (lane & 15) * 80 + (lane >> 4) * 16;

#pragma unroll
        for (int ks = 0; ks < 2; ++ks) {
            uint32_t afh[2][4], afl[2][4];
#pragma unroll
            for (int mt = 0; mt < 2; ++mt) {
                const uint32_t ao = (uint32_t)(wm * 32 + mt * 16) * 80 + ks * 32 + lrow;
                ldm4(afh[mt], sAh + ao);
                if (NT == 3) ldm4(afl[mt], sAl + ao);
            }
#pragma unroll
            for (int p = 0; p < 4; ++p) {
                uint32_t bfh[4], bfl[4];
                const uint32_t bo = (uint32_t)(wn * 64 + p * 16) * 80 + ks * 32 + lrow;
                ldm4(bfh, sBh + bo);
                if (NT == 3) ldm4(bfl, sBl + bo);
#pragma unroll
                for (int mt = 0; mt < 2; ++mt) {
                    mma16816(acc[mt][2*p],   afh[mt], bfh[0], bfh[2]);  // hi*hi
                    mma16816(acc[mt][2*p+1], afh[mt], bfh[1], bfh[3]);
                    if (NT == 3) {
                        mma16816(acc[mt][2*p],   afh[mt], bfl[0], bfl[2]);  // hi*lo
                        mma16816(acc[mt][2*p+1], afh[mt], bfl[1], bfl[3]);
                        mma16816(acc[mt][2*p],   afl[mt], bfh[0], bfh[2]);  // lo*hi
                        mma16816(acc[mt][2*p+1], afl[mt], bfh[1], bfh[3]);
                    }
                }
            }
        }
        __syncthreads();
    }

    const int l4 = lane >> 2, l2 = (lane & 3) * 2;

    if (EPI == 2) {
        // Transposed epilogue: stage hi (then lo) tile in smem, write out[e,s].
        __half* sst = (__half*)smem;          // stride 130 halves per m-row
        const int b  = row0 >> 11;            // batch (2048 rows per batch)
        const int s0 = row0 & 2047;
        __half* outs[2] = {Ch, Cl};
#pragma unroll
        for (int pass = 0; pass < 2; ++pass) {
#pragma unroll
            for (int mt = 0; mt < 2; ++mt) {
#pragma unroll
                for (int nt = 0; nt < 8; ++nt) {
                    const int rl = wm * 32 + mt * 16 + l4;
                    const int cl = wn * 64 + nt * 8 + l2;
                    const float* a = acc[mt][nt];
                    __half2 v0, v1;
                    __half h0 = __float2half(a[0]), h1 = __float2half(a[1]);
                    __half h2 = __float2half(a[2]), h3 = __float2half(a[3]);
                    if (pass == 0) {
                        v0 = __halves2half2(h0, h1);
                        v1 = __halves2half2(h2, h3);
                    } else {
                        v0 = __halves2half2(__float2half(a[0] - __half2float(h0)),
                                            __float2half(a[1] - __half2float(h1)));
                        v1 = __halves2half2(__float2half(a[2] - __half2float(h2)),
                                            __float2half(a[3] - __half2float(h3)));
                    }
                    *(__half2*)&sst[rl * 130 + cl]       = v0;
                    *(__half2*)&sst[(rl + 8) * 130 + cl] = v1;
                }
            }
            __syncthreads();
            __half* op = outs[pass];
#pragma unroll
            for (int j = 0; j < 16; ++j) {
                const int e = j * 8 + wid;
                __half v[4];
#pragma unroll
                for (int q = 0; q < 4; ++q)
                    v[q] = sst[(4 * lane + q) * 130 + e];
                const long long o = (long long)b * (1024LL * 2048) +
                                    (long long)(col0 + e) * 2048 + s0 + 4 * lane;
                *(uint2*)(op + o) = *(uint2*)v;
            }
            __syncthreads();
        }
        return;
    }

#pragma unroll
    for (int mt = 0; mt < 2; ++mt) {
#pragma unroll
        for (int nt = 0; nt < 8; ++nt) {
            const int r  = row0 + wm * 32 + mt * 16 + l4;
            const int cc = col0 + wn * 64 + nt * 8 + l2;
            const long long o0 = bz * sC + (long long)r * ldc + cc;
            const long long o1 = o0 + 8LL * ldc;
            const float* a = acc[mt][nt];
            if (EPI == 0) {
                *(float2*)(C + o0) = make_float2(a[0], a[1]);
                *(float2*)(C + o1) = make_float2(a[2], a[3]);
            } else {
                __half2 hh, ll;
                hh.x = __float2half(a[0]); hh.y = __float2half(a[1]);
                ll.x = __float2half(a[0] - __half2float(hh.x));
                ll.y = __float2half(a[1] - __half2float(hh.y));
                *(__half2*)(Ch + o0) = hh;
                *(__half2*)(Cl + o0) = ll;
                hh.x = __float2half(a[2]); hh.y = __float2half(a[3]);
                ll.x = __float2half(a[2] - __half2float(hh.x));
                ll.y = __float2half(a[3] - __half2float(hh.y));
                *(__half2*)(Ch + o1) = hh;
                *(__half2*)(Cl + o1) = ll;
            }
        }
    }
}

// ---------------- fp32 -> hi/lo fp16 split (elementwise) -------------------
__global__ __launch_bounds__(256) void split_kernel(
    const float* __restrict__ x, __half* __restrict__ h, __half* __restrict__ l)
{
    const long long i0 = ((long long)blockIdx.x * 256 + threadIdx.x) * 8;
#pragma unroll
    for (int v = 0; v < 2; ++v) {
        const float4 f = *(const float4*)(x + i0 + v * 4);
        const float ff[4] = {f.x, f.y, f.z, f.w};
        __half hh[4], ll[4];
#pragma unroll
        for (int j = 0; j < 4; ++j) {
            hh[j] = __float2half(ff[j]);
            ll[j] = __float2half(ff[j] - __half2float(hh[j]));
        }
        *(uint2*)(h + i0 + v * 4) = *(uint2*)hh;
        *(uint2*)(l + i0 + v * 4) = *(uint2*)ll;
    }
}

// ---------------- fp32 [R,C] -> transposed hi/lo fp16 [C,R] ----------------
__global__ __launch_bounds__(256) void splitT_kernel(
    const float* __restrict__ in, __half* __restrict__ oh,
    __half* __restrict__ ol, int R, int C)
{
    __shared__ float t[32][33];
    const int c0 = blockIdx.x * 32, r0 = blockIdx.y * 32;
    const int tx = threadIdx.x & 31, ty = threadIdx.x >> 5;  // 32 x 8
#pragma unroll
    for (int i = 0; i < 4; ++i)
        t[ty + 8 * i][tx] = in[(long long)(r0 + ty + 8 * i) * C + c0 + tx];
    __syncthreads();
#pragma unroll
    for (int i = 0; i < 4; ++i) {
        const float v = t[tx][ty + 8 * i];
        const __half h = __float2half(v);
        const long long o = (long long)(c0 + ty + 8 * i) * R + r0 + tx;
        oh[o] = h;
        ol[o] = __float2half(v - __half2float(h));
    }
}

// ---------------- softmax rows (2048) + fp16 hi write ----------------------
__global__ __launch_bounds__(256) void softmax_split_kernel(
    float* __restrict__ data, __half* __restrict__ wh, float scale)
{
    __shared__ float sred[256];
    const int tid = threadIdx.x;
    const long long rb = (long long)blockIdx.x * 2048;
    float* row = data + rb;

    float v[8];
    float m = -1e30f;
#pragma unroll
    for (int i = 0; i < 8; ++i) {
        v[i] = row[i * 256 + tid] * scale;
        m = fmaxf(m, v[i]);
    }
    sred[tid] = m;
    __syncthreads();
    for (int s = 128; s > 0; s >>= 1) {
        if (tid < s) sred[tid] = fmaxf(sred[tid], sred[tid + s]);
        __syncthreads();
    }
    m = sred[0];
    __syncthreads();

    float sum = 0.0f;
#pragma unroll
    for (int i = 0; i < 8; ++i) {
        v[i] = expf(v[i] - m);
        sum += v[i];
    }
    sred[tid] = sum;
    __syncthreads();
    for (int s = 128; s > 0; s >>= 1) {
        if (tid < s) sred[tid] += sred[tid + s];
        __syncthreads();
    }
    const float inv = 1.0f / sred[0];
#pragma unroll
    for (int i = 0; i < 8; ++i) {
        const float w = v[i] * inv;
        row[i * 256 + tid] = w;
        wh[rb + i * 256 + tid] = __float2half(w);
    }
}

// ---------------------------------------------------------------------------
extern "C" void kernel_launch(void* const* d_in, const int* in_sizes, int n_in,
                              void* d_out, int out_size)
{
    const float* Lt   = (const float*)d_in[0];   // [8, 2048, 1024]
    const float* rnn  = (const float*)d_in[1];   // [8, 2048, 1024]
    const float* kern = (const float*)d_in[2];   // [2, 1024, 1024]
    const float* W    = (const float*)d_in[3];   // [1024, 1024]

    float* ctx = (float*)d_out;                  // [8, 2048, 1024]
    float* wts = (float*)d_out + CTX_ELEMS;      // [8, 2048, 2048]

    __half *rnnh, *rnnl, *lth, *ltl, *wWh, *wWl, *k0h, *k0l, *k1th, *k1tl;
    __half *Ph, *Pl, *Th, *Tl, *wvth, *wvtl, *wh;
    cudaGetSymbolAddress((void**)&rnnh, g_rnn_h); cudaGetSymbolAddress((void**)&rnnl, g_rnn_l);
    cudaGetSymbolAddress((void**)&lth,  g_Lt_h);  cudaGetSymbolAddress((void**)&ltl,  g_Lt_l);
    cudaGetSymbolAddress((void**)&wWh,  g_W_h);   cudaGetSymbolAddress((void**)&wWl,  g_W_l);
    cudaGetSymbolAddress((void**)&k0h,  g_k0_h);  cudaGetSymbolAddress((void**)&k0l,  g_k0_l);
    cudaGetSymbolAddress((void**)&k1th, g_k1t_h); cudaGetSymbolAddress((void**)&k1tl, g_k1t_l);
    cudaGetSymbolAddress((void**)&Ph,   g_P_h);   cudaGetSymbolAddress((void**)&Pl,   g_P_l);
    cudaGetSymbolAddress((void**)&Th,   g_T_h);   cudaGetSymbolAddress((void**)&Tl,   g_T_l);
    cudaGetSymbolAddress((void**)&wvth, g_WVt_h); cudaGetSymbolAddress((void**)&wvtl, g_WVt_l);
    cudaGetSymbolAddress((void**)&wh,   g_w_h);

    const int SMEM3 = 2 * 4 * OP_BYTES;  // 81920
    const int SMEM1 = 2 * 2 * OP_BYTES;  // 40960
    cudaFuncSetAttribute(gemm_hmma<0,3>, cudaFuncAttributeMaxDynamicSharedMemorySize, SMEM3);
    cudaFuncSetAttribute(gemm_hmma<1,3>, cudaFuncAttributeMaxDynamicSharedMemorySize, SMEM3);
    cudaFuncSetAttribute(gemm_hmma<2,3>, cudaFuncAttributeMaxDynamicSharedMemorySize, SMEM3);
    cudaFuncSetAttribute(gemm_hmma<0,1>, cudaFuncAttributeMaxDynamicSharedMemorySize, SMEM1);

    // 1) splits: activations + small weight matrices (K-major already)
    split_kernel<<<8192, 256>>>(rnn, rnnh, rnnl);
    split_kernel<<<8192, 256>>>(Lt, lth, ltl);
    split_kernel<<<512, 256>>>(W, wWh, wWl);
    split_kernel<<<512, 256>>>(kern, k0h, k0l);
    splitT_kernel<<<dim3(32, 32, 1), 256>>>(kern + 1024 * 1024, k1th, k1tl, 1024, 1024);

    // 2) P = k0 @ W^T  [1024,1024]
    gemm_hmma<1,3><<<dim3(8, 8, 1), 256, SMEM3>>>(
        k0h, k0l, wWh, wWl, nullptr, Ph, Pl, 1024, 1024, 0, 0, 0);

    // 3) T = rnn @ P^T  [16384,1024]
    gemm_hmma<1,3><<<dim3(8, 128, 1), 256, SMEM3>>>(
        rnnh, rnnl, Ph, Pl, nullptr, Th, Tl, 1024, 1024, 0, 0, 0);

    // 4) WVt = (Lt @ k1)^T per batch  (EPI2: fused transpose + split)
    gemm_hmma<2,3><<<dim3(8, 128, 1), 256, SMEM3>>>(
        lth, ltl, k1th, k1tl, nullptr, wvth, wvtl, 1024, 0, 0, 0, 0);

    // 5) QK = T @ Lt^T per batch -> fp32 wts slab of d_out
    gemm_hmma<0,3><<<dim3(16, 16, 8), 256, SMEM3>>>(
        Th, Tl, lth, ltl, wts, nullptr, nullptr, 1024, 2048,
        2048LL * 1024, 2048LL * 1024, 2048LL * 2048);

    // 6) softmax(QK * 0.125) in place + fp16 hi for context GEMM
    softmax_split_kernel<<<16384, 256>>>(wts, wh, 0.125f);

    // 7) ctx = weights @ WVt^T per batch, K=2048, plain fp16 (1 term)
    gemm_hmma<0,1><<<dim3(8, 16, 8), 256, SMEM1>>>(
        wh, nullptr, wvth, nullptr, ctx, nullptr, nullptr, 2048, 1024,
        2048LL * 2048, 1024LL * 2048, 2048LL * 1024);
}